// round 8
// baseline (speedup 1.0000x reference)
#include <cuda_runtime.h>
#include <cuda_fp16.h>
#include <cuda_bf16.h>
#include <cstdint>

// Problem constants
#define G_   64
#define N_   2048
#define E_   16384
#define GE_  (G_ * E_)          // 1048576 edges total
#define NV_  2047               // nodes per graph excluding center
#define F_   128
#define GN_  (G_ * N_)          // 131072 node slots
#define CAP_ 64                 // per-node in-edge capacity (P(overflow) ~ 1e-35)

// ---------------- device scratch ----------------
// per node: 256 fp16 = [dis*xc (128) | dis*xr (128)]  (512 B/row)
__device__ __half g_h[(size_t)GN_ * 256];
__device__ float g_z[2048 * 256];            // per-v accum: [core(128) | red(128)]
__device__ int   g_cnt[GN_];
__device__ int   g_col[(size_t)GN_ * CAP_];  // local src ids
__device__ float g_dis[GN_];
__device__ float g_cterm[G_ * F_];
__device__ int   g_is64;
// transposed bf16 split of Wm bottom half: wt[n][k] = Wm[128+k][n]
__device__ __align__(16) __nv_bfloat16 g_wthi[128 * 128];
__device__ __align__(16) __nv_bfloat16 g_wtlo[128 * 128];

// ---------------- generic helpers ----------------
__device__ __forceinline__ unsigned long long fma2(unsigned long long a,
                                                   unsigned long long b,
                                                   unsigned long long c) {
    unsigned long long d;
    asm("fma.rn.f32x2 %0, %1, %2, %3;" : "=l"(d) : "l"(a), "l"(b), "l"(c));
    return d;
}
__device__ __forceinline__ unsigned long long pack2(float x) {
    unsigned long long d;
    asm("mov.b64 %0, {%1, %2};" : "=l"(d) : "f"(x), "f"(x));
    return d;
}
__device__ __forceinline__ void unpack2(unsigned long long v, float& lo, float& hi) {
    asm("mov.b64 {%0, %1}, %2;" : "=f"(lo), "=f"(hi) : "l"(v));
}
__device__ __forceinline__ void red4(float* p, float a, float b, float c, float d) {
    asm volatile("red.global.add.v4.f32 [%0], {%1, %2, %3, %4};"
                 :: "l"(p), "f"(a), "f"(b), "f"(c), "f"(d) : "memory");
}
__device__ __forceinline__ int edge_val(const void* ei, long idx) {
    if (g_is64) return (int)((const long long*)ei)[idx];
    return ((const int*)ei)[idx];
}
__device__ __forceinline__ void h8_to_f8(uint4 t, float* f) {
    float2 p;
    p = __half22float2(*(__half2*)&t.x); f[0] = p.x; f[1] = p.y;
    p = __half22float2(*(__half2*)&t.y); f[2] = p.x; f[3] = p.y;
    p = __half22float2(*(__half2*)&t.z); f[4] = p.x; f[5] = p.y;
    p = __half22float2(*(__half2*)&t.w); f[6] = p.x; f[7] = p.y;
}
// mma.sync m16n8k16 row.col bf16 -> fp32, accumulate in place
__device__ __forceinline__ void mma_bf16(float* c, const uint32_t* a,
                                         uint32_t b0, uint32_t b1) {
    asm volatile(
        "mma.sync.aligned.m16n8k16.row.col.f32.bf16.bf16.f32 "
        "{%0,%1,%2,%3}, {%4,%5,%6,%7}, {%8,%9}, {%0,%1,%2,%3};"
        : "+f"(c[0]), "+f"(c[1]), "+f"(c[2]), "+f"(c[3])
        : "r"(a[0]), "r"(a[1]), "r"(a[2]), "r"(a[3]), "r"(b0), "r"(b1));
}

// ---------------- init: dtype detect + zero cnt + zero z ----------------
__global__ void k_init(const void* cni) {
    int i = blockIdx.x * blockDim.x + threadIdx.x;
    if (i == 0) g_is64 = (((const int*)cni)[1] == 0) ? 1 : 0;
    if (i < GN_) g_cnt[i] = 0;
    if (i < 2048 * 256) g_z[i] = 0.0f;
}

// one pass: bucketed edge build
__global__ void k_build(const void* ei) {
    int e = blockIdx.x * blockDim.x + threadIdx.x;
    if (e < GE_) {
        int d = edge_val(ei, (long)GE_ + e);
        int s = edge_val(ei, e) & (N_ - 1);
        int slot = atomicAdd(&g_cnt[d], 1);
        if (slot < CAP_) g_col[(long)d * CAP_ + slot] = s;
    }
}

// prep: transposed bf16 hi/lo split of Wm bottom half (plain [n][k] layout)
__global__ void k_prep(const float* __restrict__ Wm) {
    int t = blockIdx.x * 256 + threadIdx.x;   // 0..16383
    int n = t >> 7, k = t & 127;
    float w = Wm[(128 + k) * 128 + n];
    __nv_bfloat16 hi = __float2bfloat16(w);
    __nv_bfloat16 lo = __float2bfloat16(w - __bfloat162float(hi));
    g_wthi[n * 128 + k] = hi;
    g_wtlo[n * 128 + k] = lo;
}

// merged: blocks [0,64) compute ce/cterm; blocks [64,320) compute g_dis
__global__ void __launch_bounds__(512)
k_ce_dis(const float* __restrict__ x, const void* cni,
         const float* __restrict__ W1, const float* __restrict__ b1,
         const float* __restrict__ Wm, const float* __restrict__ bm) {
    if (blockIdx.x >= 64) {
        int i = (blockIdx.x - 64) * 512 + threadIdx.x;
        if (i < GN_) g_dis[i] = rsqrtf(1.0f + (float)g_cnt[i]);
        return;
    }
    __shared__ float sx[128], sp[4][128], sce[128];
    int g = blockIdx.x, tid = threadIdx.x;
    int col = tid & 127, seg = tid >> 7;
    long center;
    if (g_is64) center = ((const long long*)cni)[g];
    else        center = ((const int*)cni)[g];
    if (tid < 128) sx[tid] = x[((long)g * N_ + center) * F_ + tid];
    __syncthreads();

    float s = 0.f;
    int k0 = seg * 32;
    #pragma unroll 32
    for (int k = 0; k < 32; k++) s += sx[k0 + k] * W1[(k0 + k) * 128 + col];
    sp[seg][col] = s;
    __syncthreads();
    if (seg == 0) sce[col] = b1[col] + sp[0][col] + sp[1][col] + sp[2][col] + sp[3][col];
    __syncthreads();

    float t = 0.f;
    #pragma unroll 32
    for (int k = 0; k < 32; k++) t += sce[k0 + k] * Wm[(k0 + k) * 128 + col];
    sp[seg][col] = t;
    __syncthreads();
    if (seg == 0)
        g_cterm[g * 128 + col] = bm[col] + sp[0][col] + sp[1][col] + sp[2][col] + sp[3][col];
}

// ---------------- mask GEMM via mma.sync (split-2 bf16 compensation) ------
// Block: 128 rows x 128 cols, 8 warps (4 row-groups x 2 col-groups).
// Warp: 32 rows x 64 cols = 2 m16 tiles x 8 n8 tiles, k chunked by 16.
// D = xh@Wh + xh@Wl + xl@Wh, fp32 register accumulators.
// smem rows padded to 136 bf16 = 272 B (conflict-free fragment LDS).
#define SBK_B 272
#define XHI_OFF 0
#define XLO_OFF 34816
#define WHI_OFF 69632
#define WLO_OFF 104448
#define CTS_OFF 139264
#define DIS_OFF 139776
#define SMEM_MASK_TOTAL 140288
#define STG_OFF 69632            // staged fp16 output reuses W tiles (dead)

__global__ void __launch_bounds__(256)
k_mask(const float* __restrict__ x) {
    extern __shared__ char smem[];
    const int tid = threadIdx.x;
    const int wid = tid >> 5, lane = tid & 31;
    const int g = blockIdx.y, vb = blockIdx.x;
    const int node0 = g * N_ + vb * 128;

    float* cts = (float*)(smem + CTS_OFF);
    float* dss = (float*)(smem + DIS_OFF);

    // load W^T hi/lo tiles (plain [n][k] -> padded rows)
    {
        const uint4* wh = (const uint4*)g_wthi;   // 16 uint4 per 128-elem row
        const uint4* wl = (const uint4*)g_wtlo;
        #pragma unroll
        for (int i = tid; i < 2048; i += 256) {
            int r = i >> 4, s = i & 15;
            *(uint4*)(smem + WHI_OFF + r * SBK_B + s * 16) = wh[i];
            *(uint4*)(smem + WLO_OFF + r * SBK_B + s * 16) = wl[i];
        }
    }
    // load x tile, split into bf16 hi/lo
    {
        const float4* xg = (const float4*)(x + (long)node0 * F_);
        #pragma unroll
        for (int i = tid; i < 4096; i += 256) {
            int r = i >> 5, k4 = (i & 31) * 4;
            float4 v = xg[i];
            __nv_bfloat162 h01 = __floats2bfloat162_rn(v.x, v.y);
            __nv_bfloat162 h23 = __floats2bfloat162_rn(v.z, v.w);
            float2 f01 = __bfloat1622float2(h01);
            float2 f23 = __bfloat1622float2(h23);
            __nv_bfloat162 l01 = __floats2bfloat162_rn(v.x - f01.x, v.y - f01.y);
            __nv_bfloat162 l23 = __floats2bfloat162_rn(v.z - f23.x, v.w - f23.y);
            uint2 hh, ll;
            hh.x = *(uint32_t*)&h01; hh.y = *(uint32_t*)&h23;
            ll.x = *(uint32_t*)&l01; ll.y = *(uint32_t*)&l23;
            *(uint2*)(smem + XHI_OFF + r * SBK_B + k4 * 2) = hh;
            *(uint2*)(smem + XLO_OFF + r * SBK_B + k4 * 2) = ll;
        }
    }
    if (tid < 128) {
        cts[tid] = g_cterm[g * 128 + tid];
        dss[tid] = g_dis[node0 + tid];
    }
    __syncthreads();

    const int wr = wid >> 1, wc = wid & 1;
    const int gid = lane >> 2, tig = lane & 3;

    float c[2][8][4];
    #pragma unroll
    for (int mt = 0; mt < 2; mt++)
        #pragma unroll
        for (int nt = 0; nt < 8; nt++)
            #pragma unroll
            for (int q = 0; q < 4; q++) c[mt][nt][q] = 0.f;

    #pragma unroll 1
    for (int kc = 0; kc < 8; kc++) {
        const int kb = kc * 32 + tig * 4;      // byte offset: (kc*16 + 2*tig)*2
        uint32_t ah[2][4], al[2][4];
        #pragma unroll
        for (int mt = 0; mt < 2; mt++) {
            int off = (wr * 32 + mt * 16 + gid) * SBK_B + kb;
            ah[mt][0] = *(const uint32_t*)(smem + XHI_OFF + off);
            ah[mt][1] = *(const uint32_t*)(smem + XHI_OFF + off + 8 * SBK_B);
            ah[mt][2] = *(const uint32_t*)(smem + XHI_OFF + off + 16);
            ah[mt][3] = *(const uint32_t*)(smem + XHI_OFF + off + 8 * SBK_B + 16);
            al[mt][0] = *(const uint32_t*)(smem + XLO_OFF + off);
            al[mt][1] = *(const uint32_t*)(smem + XLO_OFF + off + 8 * SBK_B);
            al[mt][2] = *(const uint32_t*)(smem + XLO_OFF + off + 16);
            al[mt][3] = *(const uint32_t*)(smem + XLO_OFF + off + 8 * SBK_B + 16);
        }
        #pragma unroll
        for (int nt = 0; nt < 8; nt++) {
            int off = (wc * 64 + nt * 8 + gid) * SBK_B + kb;
            uint32_t bh0 = *(const uint32_t*)(smem + WHI_OFF + off);
            uint32_t bh1 = *(const uint32_t*)(smem + WHI_OFF + off + 16);
            uint32_t bl0 = *(const uint32_t*)(smem + WLO_OFF + off);
            uint32_t bl1 = *(const uint32_t*)(smem + WLO_OFF + off + 16);
            #pragma unroll
            for (int mt = 0; mt < 2; mt++) {
                mma_bf16(c[mt][nt], ah[mt], bh0, bh1);
                mma_bf16(c[mt][nt], ah[mt], bl0, bl1);
                mma_bf16(c[mt][nt], al[mt], bh0, bh1);
            }
        }
    }
    __syncthreads();   // W tiles dead; staged region becomes writable

    // epilogue: relu(mask)+cterm, xc/xr, fp16, staged (stride 132 uints)
    uint32_t* staged = (uint32_t*)(smem + STG_OFF);
    #pragma unroll
    for (int mt = 0; mt < 2; mt++) {
        #pragma unroll
        for (int rr = 0; rr < 2; rr++) {
            int r = wr * 32 + mt * 16 + gid + rr * 8;
            float dv = dss[r];
            #pragma unroll
            for (int nt = 0; nt < 8; nt++) {
                int cc = wc * 64 + nt * 8 + 2 * tig;
                float d0 = c[mt][nt][rr * 2 + 0];
                float d1 = c[mt][nt][rr * 2 + 1];
                float m0 = fmaxf(d0 + cts[cc], 0.f);
                float m1 = fmaxf(d1 + cts[cc + 1], 0.f);
                uint32_t uh = *(const uint32_t*)(smem + XHI_OFF + r * SBK_B + cc * 2);
                uint32_t ul = *(const uint32_t*)(smem + XLO_OFF + r * SBK_B + cc * 2);
                float2 fh = __bfloat1622float2(*(__nv_bfloat162*)&uh);
                float2 fl = __bfloat1622float2(*(__nv_bfloat162*)&ul);
                float x0 = fh.x + fl.x, x1 = fh.y + fl.y;
                float c0 = m0 * x0, c1 = m1 * x1;
                __half2 hc = __floats2half2_rn(c0 * dv, c1 * dv);
                __half2 hr = __floats2half2_rn((x0 - c0) * dv, (x1 - c1) * dv);
                staged[r * 132 + (cc >> 1)]      = *(uint32_t*)&hc;
                staged[r * 132 + 64 + (cc >> 1)] = *(uint32_t*)&hr;
            }
        }
    }
    __syncthreads();
    // coalesced copy-out: 128 rows x 128 uints -> g_h
    #pragma unroll
    for (int i = tid; i < 4096; i += 256) {
        int row = i >> 5, q = i & 31;
        uint4 val = *(uint4*)&staged[row * 132 + q * 4];
        ((uint4*)(g_h + (long)(node0 + row) * 256))[q] = val;
    }
}

// ---------------- gather: warp per v, 8 graphs per block ----------------
__global__ void __launch_bounds__(256)
k_gather() {
    int w = threadIdx.x >> 5;
    int lane = threadIdx.x & 31;
    int v = blockIdx.x * 8 + w;
    if (v >= NV_) return;

    const uint4* base = (const uint4*)g_h;   // 32 uint4 per node row
    float acc[8];
    #pragma unroll
    for (int i = 0; i < 8; i++) acc[i] = 0.f;

    #pragma unroll
    for (int gg = 0; gg < 8; gg++) {
        int graph = blockIdx.y * 8 + gg;
        long node = (long)graph * N_ + v;
        float a[8], t[8];
        h8_to_f8(base[node * 32 + lane], a);     // self term
        int cnt = g_cnt[node];
        if (cnt > CAP_) cnt = CAP_;
        const int* col = g_col + node * CAP_;
        long gbase = (long)graph * N_;
        int e = 0;
        if (cnt & 1) {
            h8_to_f8(base[(gbase + col[0]) * 32 + lane], t);
            #pragma unroll
            for (int i = 0; i < 8; i++) a[i] += t[i];
            e = 1;
        }
        for (; e < cnt; e += 2) {
            long s0 = gbase + col[e];
            long s1 = gbase + col[e + 1];
            uint4 u0 = base[s0 * 32 + lane];
            uint4 u1 = base[s1 * 32 + lane];
            float t1[8];
            h8_to_f8(u0, t);
            h8_to_f8(u1, t1);
            #pragma unroll
            for (int i = 0; i < 8; i++) a[i] += t[i] + t1[i];
        }
        float dv = g_dis[node];
        #pragma unroll
        for (int i = 0; i < 8; i++) acc[i] += dv * a[i];
    }
    const float sc = 1.0f / (float)G_;
    float* dst = &g_z[v * 256 + lane * 8];
    red4(dst,     acc[0] * sc, acc[1] * sc, acc[2] * sc, acc[3] * sc);
    red4(dst + 4, acc[4] * sc, acc[5] * sc, acc[6] * sc, acc[7] * sc);
}

// ---------------- final tiny GEMM: out = z @ W + b ----------------
#define SROW 132
#define SMEM_FIN ((2 * 128 * SROW + 128) * 4)
__global__ void __launch_bounds__(512)
k_final(const float* __restrict__ W2, const float* __restrict__ b2,
        const float* __restrict__ W3, const float* __restrict__ b3,
        float* __restrict__ out) {
    extern __shared__ float sm[];
    float* zs = sm;
    float* ws = sm + 128 * SROW;
    float* bs = sm + 2 * 128 * SROW;

    const int half = blockIdx.y;       // 0 = core (W2), 1 = red (W3)
    const int rb = blockIdx.x * 128;
    const int tid = threadIdx.x;
    const float* W = half ? W3 : W2;
    const float* B = half ? b3 : b2;

    const float4* wv = (const float4*)W;
    const float4* zv = (const float4*)g_z;
    #pragma unroll
    for (int i = tid; i < 4096; i += 512) {
        int r = i >> 5, c4 = i & 31;
        *(float4*)&ws[r * SROW + c4 * 4] = wv[i];
        int rg = rb + r;
        float4 zt = make_float4(0.f, 0.f, 0.f, 0.f);
        if (rg < NV_) zt = zv[(long)rg * 64 + half * 32 + c4];
        *(float4*)&zs[r * SROW + c4 * 4] = zt;
    }
    if (tid < 128) bs[tid] = B[tid];
    __syncthreads();

    const int ty = tid >> 4, tx = tid & 15;
    const int r0 = ty * 4, c0 = tx * 8;

    unsigned long long acc[4][4];
    #pragma unroll
    for (int i = 0; i < 4; i++)
        #pragma unroll
        for (int j = 0; j < 4; j++) acc[i][j] = 0ull;

    #pragma unroll 4
    for (int k = 0; k < 128; k++) {
        double2 b01 = *(const double2*)&ws[k * SROW + c0];
        double2 b23 = *(const double2*)&ws[k * SROW + c0 + 4];
        unsigned long long bb0 = __double_as_longlong(b01.x);
        unsigned long long bb1 = __double_as_longlong(b01.y);
        unsigned long long bb2 = __double_as_longlong(b23.x);
        unsigned long long bb3 = __double_as_longlong(b23.y);
        #pragma unroll
        for (int i = 0; i < 4; i++) {
            unsigned long long ap = pack2(zs[(r0 + i) * SROW + k]);
            acc[i][0] = fma2(ap, bb0, acc[i][0]);
            acc[i][1] = fma2(ap, bb1, acc[i][1]);
            acc[i][2] = fma2(ap, bb2, acc[i][2]);
            acc[i][3] = fma2(ap, bb3, acc[i][3]);
        }
    }

    float* ob = out + (long)half * NV_ * 128;
    #pragma unroll
    for (int i = 0; i < 4; i++) {
        int rg = rb + r0 + i;
        if (rg >= NV_) continue;
        float v0, v1, v2, v3, v4, v5, v6, v7;
        unpack2(acc[i][0], v0, v1); unpack2(acc[i][1], v2, v3);
        unpack2(acc[i][2], v4, v5); unpack2(acc[i][3], v6, v7);
        float* dst = ob + (long)rg * 128 + c0;
        *(float4*)dst       = make_float4(v0 + bs[c0],     v1 + bs[c0 + 1],
                                          v2 + bs[c0 + 2], v3 + bs[c0 + 3]);
        *(float4*)(dst + 4) = make_float4(v4 + bs[c0 + 4], v5 + bs[c0 + 5],
                                          v6 + bs[c0 + 6], v7 + bs[c0 + 7]);
    }
}

// ---------------- launch ----------------
extern "C" void kernel_launch(void* const* d_in, const int* in_sizes, int n_in,
                              void* d_out, int out_size) {
    const float* x   = (const float*)d_in[0];
    const void*  ei  = d_in[1];
    const void*  cni = d_in[3];
    const float* W1  = (const float*)d_in[4];
    const float* b1  = (const float*)d_in[5];
    const float* W2  = (const float*)d_in[6];
    const float* b2  = (const float*)d_in[7];
    const float* W3  = (const float*)d_in[8];
    const float* b3  = (const float*)d_in[9];
    const float* Wm  = (const float*)d_in[10];
    const float* bm  = (const float*)d_in[11];
    float* out = (float*)d_out;

    cudaFuncSetAttribute(k_mask, cudaFuncAttributeMaxDynamicSharedMemorySize,
                         SMEM_MASK_TOTAL);
    cudaFuncSetAttribute(k_final, cudaFuncAttributeMaxDynamicSharedMemorySize,
                         SMEM_FIN);

    k_init<<<2048, 256>>>(cni);
    k_build<<<GE_ / 256, 256>>>(ei);
    k_prep<<<64, 256>>>(Wm);
    k_ce_dis<<<64 + GN_ / 512, 512>>>(x, cni, W1, b1, Wm, bm);
    k_mask<<<dim3(16, 64), 256, SMEM_MASK_TOTAL>>>(x);
    k_gather<<<dim3(256, 8), 256>>>();
    k_final<<<dim3(16, 2), 512, SMEM_FIN>>>(W2, b2, W3, b3, out);
}